// round 9
// baseline (speedup 1.0000x reference)
#include <cuda_runtime.h>
#include <cuda_fp16.h>
#include <cstdint>

#define N_NODES 100000
#define N_EDGES 1600000
#define N_GRAPHS 64

// ---------------- device scratch (allocations forbidden) ----------------
__device__ float g_agg[(size_t)N_NODES * 128];            // 51.2 MB
__device__ float g_ugb[N_GRAPHS * 256];                   // b1 + u@W1u per graph
__device__ __align__(16) __half g_W1t[256 * 256];         // W1[0:256]^T fp16, [n][k]
__device__ __align__(16) __half g_W2t[128 * 256];         // W2^T fp16, [n][k]
__device__ int g_cnt[N_NODES];                            // degree counters (self-restoring)
__device__ int g_off[N_NODES + 1];                        // CSR offsets
__device__ int g_bucket[N_EDGES];                         // edge ids grouped by dst

// ---------------- helpers ----------------
__device__ __forceinline__ void mma16(float* c, const unsigned* a, unsigned b0, unsigned b1) {
    asm volatile(
        "mma.sync.aligned.m16n8k16.row.col.f32.f16.f16.f32 "
        "{%0,%1,%2,%3}, {%4,%5,%6,%7}, {%8,%9}, {%0,%1,%2,%3};"
        : "+f"(c[0]), "+f"(c[1]), "+f"(c[2]), "+f"(c[3])
        : "r"(a[0]), "r"(a[1]), "r"(a[2]), "r"(a[3]), "r"(b0), "r"(b1));
}

__device__ __forceinline__ void cp16(void* dst_smem, const void* src) {
    unsigned d = (unsigned)__cvta_generic_to_shared(dst_smem);
    asm volatile("cp.async.ca.shared.global [%0], [%1], 16;" :: "r"(d), "l"(src) : "memory");
}
#define CP_COMMIT() asm volatile("cp.async.commit_group;" ::: "memory")
#define CP_WAIT(n)  asm volatile("cp.async.wait_group %0;" :: "n"(n) : "memory")

// ---------------- merged prep: W1^T fp16 | W2^T fp16 | ugb | zero cnt ----------------
// blocks [0,256): W1t ; [256,384): W2t ; [384,448): ugb ; [448,839): zero cnt
__global__ void prep_kernel(const float* __restrict__ W1, const float* __restrict__ W2,
                            const float* __restrict__ u, const float* __restrict__ b1) {
    int bid = blockIdx.x;
    if (bid < 256) {
        int idx = bid * 256 + threadIdx.x;
        int n = idx >> 8, k = idx & 255;
        g_W1t[n * 256 + k] = __float2half_rn(W1[k * 256 + n]);
    } else if (bid < 384) {
        int idx = (bid - 256) * 256 + threadIdx.x;
        int n = idx >> 8, k = idx & 255;
        g_W2t[n * 256 + k] = __float2half_rn(W2[k * 128 + n]);
    } else if (bid < 448) {
        int g = bid - 384, n = threadIdx.x;
        float acc = b1[n];
#pragma unroll
        for (int j = 0; j < 16; j++) acc += u[g * 16 + j] * W1[(256 + j) * 256 + n];
        g_ugb[g * 256 + n] = acc;
    } else {
        int i = (bid - 448) * 256 + threadIdx.x;
        if (i < N_NODES) g_cnt[i] = 0;
    }
}

// ---------------- CSR build ----------------
__global__ void hist_kernel(const int* __restrict__ col) {
    int e = blockIdx.x * 256 + threadIdx.x;
    if (e >= N_EDGES) return;
    int c = __ldg(col + e);
    if ((unsigned)c < N_NODES) atomicAdd(&g_cnt[c], 1);
}

#define SCAN_T 1024
#define SCAN_C 98
__global__ void scan_kernel() {
    __shared__ int part[SCAN_T];
    int t = threadIdx.x;
    int lo = t * SCAN_C, hi = min(lo + SCAN_C, N_NODES);
    int s = 0;
    for (int i = lo; i < hi; i++) s += g_cnt[i];
    part[t] = s;
    __syncthreads();
    for (int d = 1; d < SCAN_T; d <<= 1) {
        int v = (t >= d) ? part[t - d] : 0;
        __syncthreads();
        part[t] += v;
        __syncthreads();
    }
    int run = (t == 0) ? 0 : part[t - 1];
    for (int i = lo; i < hi; i++) {
        g_off[i] = run;
        run += g_cnt[i];
    }
    if (t == SCAN_T - 1) g_off[N_NODES] = run;
}

__global__ void fill_kernel(const int* __restrict__ col) {
    int e = blockIdx.x * 256 + threadIdx.x;
    if (e >= N_EDGES) return;
    int c = __ldg(col + e);
    if ((unsigned)c >= N_NODES) return;
    int old = atomicAdd(&g_cnt[c], -1);      // counts down to 0 -> cnt self-restored
    g_bucket[g_off[c] + old - 1] = e;
}

// ---------------- gather: warp per node, shuffle-broadcast indices, MLP=4 payloads ----------------
__global__ void gather_kernel(const float* __restrict__ ea) {
    int n = blockIdx.x * 8 + (threadIdx.x >> 5);
    if (n >= N_NODES) return;
    int l = threadIdx.x & 31;
    int beg = g_off[n], end = g_off[n + 1];
    float4 acc = make_float4(0.f, 0.f, 0.f, 0.f);
    for (int s = beg; s < end; s += 32) {
        int cnt = min(32, end - s);
        int myE = (s + l < end) ? __ldg(g_bucket + s + l) : 0;   // one coalesced index load
        int j = 0;
        for (; j + 4 <= cnt; j += 4) {
            int e0 = __shfl_sync(0xFFFFFFFF, myE, j);
            int e1 = __shfl_sync(0xFFFFFFFF, myE, j + 1);
            int e2 = __shfl_sync(0xFFFFFFFF, myE, j + 2);
            int e3 = __shfl_sync(0xFFFFFFFF, myE, j + 3);
            float4 v0 = __ldcs((const float4*)(ea + (size_t)e0 * 128) + l);
            float4 v1 = __ldcs((const float4*)(ea + (size_t)e1 * 128) + l);
            float4 v2 = __ldcs((const float4*)(ea + (size_t)e2 * 128) + l);
            float4 v3 = __ldcs((const float4*)(ea + (size_t)e3 * 128) + l);
            acc.x += (v0.x + v1.x) + (v2.x + v3.x);
            acc.y += (v0.y + v1.y) + (v2.y + v3.y);
            acc.z += (v0.z + v1.z) + (v2.z + v3.z);
            acc.w += (v0.w + v1.w) + (v2.w + v3.w);
        }
        for (; j < cnt; j++) {
            int e0 = __shfl_sync(0xFFFFFFFF, myE, j);
            float4 v0 = __ldcs((const float4*)(ea + (size_t)e0 * 128) + l);
            acc.x += v0.x; acc.y += v0.y; acc.z += v0.z; acc.w += v0.w;
        }
    }
    *(((float4*)(g_agg + (size_t)n * 128)) + l) = acc;
}

// ---------------- fused 2-layer MLP (fp16 mma, 512 threads/16 warps) — unchanged ----------------
#define HS2 132
#define WSB 20
#define HS_BYTES (128 * HS2 * 4)
#define B1BUF (256 * WSB)
#define B2BUF (128 * WSB)
#define WSL_BYTES (2 * B1BUF * 4)
#define SMEM_TOTAL (HS_BYTES + WSL_BYTES + 1024)

__global__ void __launch_bounds__(512, 1) mlp_kernel(
    const float* __restrict__ x, const int* __restrict__ batch,
    const float* __restrict__ b2, float* __restrict__ out)
{
    extern __shared__ unsigned char sm[];
    unsigned* hs  = (unsigned*)sm;
    unsigned* wsl = (unsigned*)(sm + HS_BYTES);
    int*      gb  = (int*)(sm + HS_BYTES + WSL_BYTES);
    float*    b2s = (float*)(sm + HS_BYTES + WSL_BYTES + 512);

    const int tid  = threadIdx.x;
    const int wid  = tid >> 5;
    const int lane = tid & 31;
    const int g    = lane >> 2;
    const int t    = lane & 3;
    const int base = blockIdx.x * 128;
    const int wm   = (wid >> 2) * 32;
    const int wn   = (wid & 3) * 64;

    {
#pragma unroll
        for (int i = 0; i < 2; i++) {
            int q = tid + i * 512;
            int n = q >> 2, j = q & 3;
            cp16((char*)wsl + n * 80 + j * 16, (const char*)g_W1t + n * 512 + j * 16);
        }
        CP_COMMIT();
    }

    if (tid < 128) {
        int node = min(base + tid, N_NODES - 1);
        int gv = batch[node];
        gb[tid]  = min(max(gv, 0), N_GRAPHS - 1);
        b2s[tid] = b2[tid];
    }

#pragma unroll
    for (int i = 0; i < 16; i++) {
        int uq = tid + i * 512;
        int r = uq >> 6, c4 = (uq & 63) << 2;
        int node = base + r;
        float4 v = make_float4(0.f, 0.f, 0.f, 0.f);
        if (node < N_NODES) {
            v = (c4 < 128)
                ? __ldg((const float4*)(x + (size_t)node * 128 + c4))
                : __ldg((const float4*)(g_agg + (size_t)node * 128 + (c4 - 128)));
        }
        __half2 h0 = __floats2half2_rn(v.x, v.y);
        __half2 h1 = __floats2half2_rn(v.z, v.w);
        uint2 o; o.x = *(unsigned*)&h0; o.y = *(unsigned*)&h1;
        *(uint2*)(hs + r * HS2 + (c4 >> 1)) = o;
    }

    float acc[2][8][4];
#pragma unroll
    for (int a = 0; a < 2; a++)
#pragma unroll
        for (int b = 0; b < 8; b++)
#pragma unroll
            for (int q = 0; q < 4; q++) acc[a][b][q] = 0.f;

#pragma unroll 1
    for (int c = 0; c < 8; c++) {
        if (c < 7) {
            unsigned* dst = wsl + ((c + 1) & 1) * B1BUF;
            const char* src = (const char*)g_W1t + (c + 1) * 64;
#pragma unroll
            for (int i = 0; i < 2; i++) {
                int q = tid + i * 512;
                int n = q >> 2, j = q & 3;
                cp16((char*)dst + n * 80 + j * 16, src + n * 512 + j * 16);
            }
            CP_COMMIT(); CP_WAIT(1);
        } else {
            CP_WAIT(0);
        }
        __syncthreads();
        const unsigned* wb = wsl + (c & 1) * B1BUF;
#pragma unroll
        for (int ks = 0; ks < 2; ks++) {
            const int kg2 = c * 16 + ks * 8;
            const int kb2 = ks * 8;
            unsigned a_[2][4];
#pragma unroll
            for (int mf = 0; mf < 2; mf++) {
                int r0 = (wm + mf * 16 + g) * HS2;
                int r1 = r0 + 8 * HS2;
                a_[mf][0] = hs[r0 + kg2 + t];
                a_[mf][1] = hs[r1 + kg2 + t];
                a_[mf][2] = hs[r0 + kg2 + t + 4];
                a_[mf][3] = hs[r1 + kg2 + t + 4];
            }
#pragma unroll
            for (int nf = 0; nf < 8; nf++) {
                int n = wn + nf * 8 + g;
                unsigned b0 = wb[n * WSB + kb2 + t];
                unsigned b1 = wb[n * WSB + kb2 + t + 4];
#pragma unroll
                for (int mf = 0; mf < 2; mf++)
                    mma16(acc[mf][nf], a_[mf], b0, b1);
            }
        }
        __syncthreads();
    }

    {
        int n = tid >> 2, j = tid & 3;
        cp16((char*)wsl + n * 80 + j * 16, (const char*)g_W2t + n * 512 + j * 16);
        CP_COMMIT();
    }

#pragma unroll
    for (int mf = 0; mf < 2; mf++) {
        int r0 = wm + mf * 16 + g;
        int r1 = r0 + 8;
        const float* u0 = g_ugb + gb[r0] * 256;
        const float* u1 = g_ugb + gb[r1] * 256;
#pragma unroll
        for (int nf = 0; nf < 8; nf++) {
            int n0 = wn + nf * 8 + 2 * t;
            float f0 = fmaxf(acc[mf][nf][0] + u0[n0], 0.f);
            float f1 = fmaxf(acc[mf][nf][1] + u0[n0 + 1], 0.f);
            float f2 = fmaxf(acc[mf][nf][2] + u1[n0], 0.f);
            float f3 = fmaxf(acc[mf][nf][3] + u1[n0 + 1], 0.f);
            __half2 p0 = __floats2half2_rn(f0, f1);
            __half2 p1 = __floats2half2_rn(f2, f3);
            hs[r0 * HS2 + (n0 >> 1)] = *(unsigned*)&p0;
            hs[r1 * HS2 + (n0 >> 1)] = *(unsigned*)&p1;
        }
    }
    __syncthreads();

    const int wn2 = (wid & 3) * 32;
    float acc2[2][4][4];
#pragma unroll
    for (int a = 0; a < 2; a++)
#pragma unroll
        for (int b = 0; b < 4; b++)
#pragma unroll
            for (int q = 0; q < 4; q++) acc2[a][b][q] = 0.f;

#pragma unroll 1
    for (int c = 0; c < 8; c++) {
        if (c < 7) {
            unsigned* dst = wsl + ((c + 1) & 1) * B2BUF;
            const char* src = (const char*)g_W2t + (c + 1) * 64;
            {
                int q = tid;
                int n = q >> 2, j = q & 3;
                cp16((char*)dst + n * 80 + j * 16, src + n * 512 + j * 16);
            }
            CP_COMMIT(); CP_WAIT(1);
        } else {
            CP_WAIT(0);
        }
        __syncthreads();
        const unsigned* wb = wsl + (c & 1) * B2BUF;
#pragma unroll
        for (int ks = 0; ks < 2; ks++) {
            const int kg2 = c * 16 + ks * 8;
            const int kb2 = ks * 8;
            unsigned a_[2][4];
#pragma unroll
            for (int mf = 0; mf < 2; mf++) {
                int r0 = (wm + mf * 16 + g) * HS2;
                int r1 = r0 + 8 * HS2;
                a_[mf][0] = hs[r0 + kg2 + t];
                a_[mf][1] = hs[r1 + kg2 + t];
                a_[mf][2] = hs[r0 + kg2 + t + 4];
                a_[mf][3] = hs[r1 + kg2 + t + 4];
            }
#pragma unroll
            for (int nf = 0; nf < 4; nf++) {
                int n = wn2 + nf * 8 + g;
                unsigned b0 = wb[n * WSB + kb2 + t];
                unsigned b1 = wb[n * WSB + kb2 + t + 4];
#pragma unroll
                for (int mf = 0; mf < 2; mf++)
                    mma16(acc2[mf][nf], a_[mf], b0, b1);
            }
        }
        __syncthreads();
    }

#pragma unroll
    for (int mf = 0; mf < 2; mf++) {
        int r0 = wm + mf * 16 + g;
        int r1 = r0 + 8;
        int node0 = base + r0;
        int node1 = base + r1;
#pragma unroll
        for (int nf = 0; nf < 4; nf++) {
            int col = wn2 + nf * 8 + 2 * t;
            if (node0 < N_NODES) {
                float2 xv = *(const float2*)(x + (size_t)node0 * 128 + col);
                float2 o;
                o.x = acc2[mf][nf][0] + b2s[col] + xv.x;
                o.y = acc2[mf][nf][1] + b2s[col + 1] + xv.y;
                *(float2*)(out + (size_t)node0 * 128 + col) = o;
            }
            if (node1 < N_NODES) {
                float2 xv = *(const float2*)(x + (size_t)node1 * 128 + col);
                float2 o;
                o.x = acc2[mf][nf][2] + b2s[col] + xv.x;
                o.y = acc2[mf][nf][3] + b2s[col + 1] + xv.y;
                *(float2*)(out + (size_t)node1 * 128 + col) = o;
            }
        }
    }
}

// ---------------- launch ----------------
extern "C" void kernel_launch(void* const* d_in, const int* in_sizes, int n_in,
                              void* d_out, int out_size) {
    const float* x = nullptr; const int* edge_index = nullptr; const float* edge_attr = nullptr;
    const float* u = nullptr; const int* batch = nullptr;
    const float* W1 = nullptr; const float* b1 = nullptr;
    const float* W2 = nullptr; const float* b2 = nullptr;

    for (int i = 0; i < n_in; i++) {
        switch (in_sizes[i]) {
            case 12800000:  x          = (const float*)d_in[i]; break;
            case 3200000:   edge_index = (const int*)d_in[i];   break;
            case 204800000: edge_attr  = (const float*)d_in[i]; break;
            case 1024:      u          = (const float*)d_in[i]; break;
            case 100000:    batch      = (const int*)d_in[i];   break;
            case 69632:     W1         = (const float*)d_in[i]; break;
            case 256:       b1         = (const float*)d_in[i]; break;
            case 32768:     W2         = (const float*)d_in[i]; break;
            case 128:       b2         = (const float*)d_in[i]; break;
            default: break;
        }
    }
    float* out = (float*)d_out;
    const int* col = edge_index + N_EDGES;

    cudaFuncSetAttribute(mlp_kernel, cudaFuncAttributeMaxDynamicSharedMemorySize, SMEM_TOTAL);

    prep_kernel<<<448 + (N_NODES + 255) / 256, 256>>>(W1, W2, u, b1);
    hist_kernel<<<(N_EDGES + 255) / 256, 256>>>(col);
    scan_kernel<<<1, SCAN_T>>>();
    fill_kernel<<<(N_EDGES + 255) / 256, 256>>>(col);
    gather_kernel<<<(N_NODES + 7) / 8, 256>>>(edge_attr);
    mlp_kernel<<<(N_NODES + 127) / 128, 512, SMEM_TOTAL>>>(x, batch, b2, out);
}

// round 10
// speedup vs baseline: 1.2511x; 1.2511x over previous
#include <cuda_runtime.h>
#include <cuda_fp16.h>
#include <cstdint>

#define N_NODES 100000
#define N_EDGES 1600000
#define N_GRAPHS 64

// ---------------- device scratch (allocations forbidden) ----------------
__device__ float g_agg[(size_t)N_NODES * 128];            // 51.2 MB
__device__ float g_acc1[(size_t)N_NODES * 256];           // 102.4 MB: x@W1x + ugb partial
__device__ float g_ugb[N_GRAPHS * 256];                   // b1 + u@W1u per graph
__device__ __align__(16) __half g_W1t[256 * 256];         // W1[0:256]^T fp16, [n][k]
__device__ __align__(16) __half g_W2t[128 * 256];         // W2^T fp16, [n][k]

// ---------------- helpers ----------------
__device__ __forceinline__ void mma16(float* c, const unsigned* a, unsigned b0, unsigned b1) {
    asm volatile(
        "mma.sync.aligned.m16n8k16.row.col.f32.f16.f16.f32 "
        "{%0,%1,%2,%3}, {%4,%5,%6,%7}, {%8,%9}, {%0,%1,%2,%3};"
        : "+f"(c[0]), "+f"(c[1]), "+f"(c[2]), "+f"(c[3])
        : "r"(a[0]), "r"(a[1]), "r"(a[2]), "r"(a[3]), "r"(b0), "r"(b1));
}

__device__ __forceinline__ void cp16(void* dst_smem, const void* src) {
    unsigned d = (unsigned)__cvta_generic_to_shared(dst_smem);
    asm volatile("cp.async.ca.shared.global [%0], [%1], 16;" :: "r"(d), "l"(src) : "memory");
}
#define CP_COMMIT() asm volatile("cp.async.commit_group;" ::: "memory")
#define CP_WAIT(n)  asm volatile("cp.async.wait_group %0;" :: "n"(n) : "memory")

// ---------------- prep: W1^T fp16 | W2^T fp16 | ugb ----------------
__global__ void prep_kernel(const float* __restrict__ W1, const float* __restrict__ W2,
                            const float* __restrict__ u, const float* __restrict__ b1) {
    int bid = blockIdx.x;
    if (bid < 256) {
        int idx = bid * 256 + threadIdx.x;
        int n = idx >> 8, k = idx & 255;
        g_W1t[n * 256 + k] = __float2half_rn(W1[k * 256 + n]);
    } else if (bid < 384) {
        int idx = (bid - 256) * 256 + threadIdx.x;
        int n = idx >> 8, k = idx & 255;
        g_W2t[n * 256 + k] = __float2half_rn(W2[k * 128 + n]);
    } else {
        int g = bid - 384, n = threadIdx.x;
        float acc = b1[n];
#pragma unroll
        for (int j = 0; j < 16; j++) acc += u[g * 16 + j] * W1[(256 + j) * 256 + n];
        g_ugb[g * 256 + n] = acc;
    }
}

// ---------------- edge scatter (lean 2-edge form for co-residency) ----------------
__global__ void scatter_kernel(const float* __restrict__ ea, const int* __restrict__ col) {
    int w = blockIdx.x * 8 + (threadIdx.x >> 5);
    int l = threadIdx.x & 31;
    int e0 = w * 2, e1 = e0 + 1;
    int c0 = __ldg(col + e0), c1 = __ldg(col + e1);
    float4 v0 = __ldcs((const float4*)(ea + (size_t)e0 * 128) + l);
    float4 v1 = __ldcs((const float4*)(ea + (size_t)e1 * 128) + l);
    if ((unsigned)c0 < N_NODES) atomicAdd(((float4*)(g_agg + (size_t)c0 * 128)) + l, v0);
    if ((unsigned)c1 < N_NODES) atomicAdd(((float4*)(g_agg + (size_t)c1 * 128)) + l, v1);
}

// ---------------- shared tiling constants ----------------
#define HS2 132                      // mlp_b hs row stride (half2)
#define HS2A 68                      // mlp_a hs row stride (half2)
#define WSB 20                       // B chunk row stride (half2)
#define B1BUF (256 * WSB)
#define B2BUF (128 * WSB)
#define WSL_BYTES (2 * B1BUF * 4)    // 40960
#define HSA_BYTES (128 * HS2A * 4)   // 34816
#define HS_BYTES (128 * HS2 * 4)     // 67584
#define SMA_TOTAL (HSA_BYTES + WSL_BYTES + 512)
#define SMB_TOTAL (HS_BYTES + WSL_BYTES + 512)

// ---------------- mlp_a: acc1 = x @ W1[0:128] + ugb[batch]  (runs under scatter) ----------------
__global__ void __launch_bounds__(512, 1) mlp_a_kernel(
    const float* __restrict__ x, const int* __restrict__ batch)
{
    extern __shared__ unsigned char sm[];
    unsigned* hs  = (unsigned*)sm;
    unsigned* wsl = (unsigned*)(sm + HSA_BYTES);
    int*      gb  = (int*)(sm + HSA_BYTES + WSL_BYTES);

    const int tid  = threadIdx.x;
    const int wid  = tid >> 5;
    const int lane = tid & 31;
    const int g    = lane >> 2;
    const int t    = lane & 3;
    const int base = blockIdx.x * 128;
    const int wm   = (wid >> 2) * 32;
    const int wn   = (wid & 3) * 64;

    {   // prefetch W1 chunk 0 (k 0..31)
#pragma unroll
        for (int i = 0; i < 2; i++) {
            int q = tid + i * 512;
            int n = q >> 2, j = q & 3;
            cp16((char*)wsl + n * 80 + j * 16, (const char*)g_W1t + n * 512 + j * 16);
        }
        CP_COMMIT();
    }

    if (tid < 128) {
        int node = min(base + tid, N_NODES - 1);
        gb[tid] = min(max(batch[node], 0), N_GRAPHS - 1);
    }

    // fill hs = fp16(x) : 128 rows x 128 cols (4096 float4)
#pragma unroll
    for (int i = 0; i < 8; i++) {
        int q = tid + i * 512;
        int r = q >> 5, c4 = (q & 31) << 2;
        int node = base + r;
        float4 v = make_float4(0.f, 0.f, 0.f, 0.f);
        if (node < N_NODES) v = __ldg((const float4*)(x + (size_t)node * 128 + c4));
        __half2 h0 = __floats2half2_rn(v.x, v.y);
        __half2 h1 = __floats2half2_rn(v.z, v.w);
        uint2 o; o.x = *(unsigned*)&h0; o.y = *(unsigned*)&h1;
        *(uint2*)(hs + r * HS2A + (c4 >> 1)) = o;
    }

    float acc[2][8][4];
#pragma unroll
    for (int a = 0; a < 2; a++)
#pragma unroll
        for (int b = 0; b < 8; b++)
#pragma unroll
            for (int q = 0; q < 4; q++) acc[a][b][q] = 0.f;

#pragma unroll 1
    for (int c = 0; c < 4; c++) {
        if (c < 3) {
            unsigned* dst = wsl + ((c + 1) & 1) * B1BUF;
            const char* src = (const char*)g_W1t + (c + 1) * 64;
#pragma unroll
            for (int i = 0; i < 2; i++) {
                int q = tid + i * 512;
                int n = q >> 2, j = q & 3;
                cp16((char*)dst + n * 80 + j * 16, src + n * 512 + j * 16);
            }
            CP_COMMIT(); CP_WAIT(1);
        } else {
            CP_WAIT(0);
        }
        __syncthreads();
        const unsigned* wb = wsl + (c & 1) * B1BUF;
#pragma unroll
        for (int ks = 0; ks < 2; ks++) {
            const int kg2 = c * 16 + ks * 8;
            const int kb2 = ks * 8;
            unsigned a_[2][4];
#pragma unroll
            for (int mf = 0; mf < 2; mf++) {
                int r0 = (wm + mf * 16 + g) * HS2A;
                int r1 = r0 + 8 * HS2A;
                a_[mf][0] = hs[r0 + kg2 + t];
                a_[mf][1] = hs[r1 + kg2 + t];
                a_[mf][2] = hs[r0 + kg2 + t + 4];
                a_[mf][3] = hs[r1 + kg2 + t + 4];
            }
#pragma unroll
            for (int nf = 0; nf < 8; nf++) {
                int n = wn + nf * 8 + g;
                unsigned b0 = wb[n * WSB + kb2 + t];
                unsigned b1 = wb[n * WSB + kb2 + t + 4];
#pragma unroll
                for (int mf = 0; mf < 2; mf++)
                    mma16(acc[mf][nf], a_[mf], b0, b1);
            }
        }
        __syncthreads();
    }

    // epilogue: acc1 = acc + ugb[batch]
#pragma unroll
    for (int mf = 0; mf < 2; mf++) {
        int r0 = wm + mf * 16 + g;
        int r1 = r0 + 8;
        int node0 = base + r0;
        int node1 = base + r1;
        const float* u0 = g_ugb + gb[r0] * 256;
        const float* u1 = g_ugb + gb[r1] * 256;
#pragma unroll
        for (int nf = 0; nf < 8; nf++) {
            int n0 = wn + nf * 8 + 2 * t;
            if (node0 < N_NODES) {
                float2 o;
                o.x = acc[mf][nf][0] + u0[n0];
                o.y = acc[mf][nf][1] + u0[n0 + 1];
                *(float2*)(g_acc1 + (size_t)node0 * 256 + n0) = o;
            }
            if (node1 < N_NODES) {
                float2 o;
                o.x = acc[mf][nf][2] + u1[n0];
                o.y = acc[mf][nf][3] + u1[n0 + 1];
                *(float2*)(g_acc1 + (size_t)node1 * 256 + n0) = o;
            }
        }
    }
}

// ---------------- mlp_b: h1 = relu(acc1 + agg @ W1[128:256]); out = h1 @ W2 + b2 + x ----------------
__global__ void __launch_bounds__(512, 1) mlp_b_kernel(
    const float* __restrict__ x, const float* __restrict__ b2, float* __restrict__ out)
{
    extern __shared__ unsigned char sm[];
    unsigned* hs  = (unsigned*)sm;
    unsigned* wsl = (unsigned*)(sm + HS_BYTES);
    float*    b2s = (float*)(sm + HS_BYTES + WSL_BYTES);

    const int tid  = threadIdx.x;
    const int wid  = tid >> 5;
    const int lane = tid & 31;
    const int g    = lane >> 2;
    const int t    = lane & 3;
    const int base = blockIdx.x * 128;
    const int wm   = (wid >> 2) * 32;
    const int wn   = (wid & 3) * 64;

    {   // prefetch W1 agg-part chunk 0 (k 128..159)
#pragma unroll
        for (int i = 0; i < 2; i++) {
            int q = tid + i * 512;
            int n = q >> 2, j = q & 3;
            cp16((char*)wsl + n * 80 + j * 16, (const char*)g_W1t + 256 + n * 512 + j * 16);
        }
        CP_COMMIT();
    }

    if (tid < 128) b2s[tid] = b2[tid];

    // fill hs = fp16(agg) : 128 rows x 128 cols
#pragma unroll
    for (int i = 0; i < 8; i++) {
        int q = tid + i * 512;
        int r = q >> 5, c4 = (q & 31) << 2;
        int node = base + r;
        float4 v = make_float4(0.f, 0.f, 0.f, 0.f);
        if (node < N_NODES) v = __ldg((const float4*)(g_agg + (size_t)node * 128 + c4));
        __half2 h0 = __floats2half2_rn(v.x, v.y);
        __half2 h1 = __floats2half2_rn(v.z, v.w);
        uint2 o; o.x = *(unsigned*)&h0; o.y = *(unsigned*)&h1;
        *(uint2*)(hs + r * HS2 + (c4 >> 1)) = o;
    }

    float acc[2][8][4];
#pragma unroll
    for (int a = 0; a < 2; a++)
#pragma unroll
        for (int b = 0; b < 8; b++)
#pragma unroll
            for (int q = 0; q < 4; q++) acc[a][b][q] = 0.f;

#pragma unroll 1
    for (int c = 0; c < 4; c++) {
        if (c < 3) {
            unsigned* dst = wsl + ((c + 1) & 1) * B1BUF;
            const char* src = (const char*)g_W1t + 256 + (c + 1) * 64;
#pragma unroll
            for (int i = 0; i < 2; i++) {
                int q = tid + i * 512;
                int n = q >> 2, j = q & 3;
                cp16((char*)dst + n * 80 + j * 16, src + n * 512 + j * 16);
            }
            CP_COMMIT(); CP_WAIT(1);
        } else {
            CP_WAIT(0);
        }
        __syncthreads();
        const unsigned* wb = wsl + (c & 1) * B1BUF;
#pragma unroll
        for (int ks = 0; ks < 2; ks++) {
            const int kg2 = c * 16 + ks * 8;
            const int kb2 = ks * 8;
            unsigned a_[2][4];
#pragma unroll
            for (int mf = 0; mf < 2; mf++) {
                int r0 = (wm + mf * 16 + g) * HS2;
                int r1 = r0 + 8 * HS2;
                a_[mf][0] = hs[r0 + kg2 + t];
                a_[mf][1] = hs[r1 + kg2 + t];
                a_[mf][2] = hs[r0 + kg2 + t + 4];
                a_[mf][3] = hs[r1 + kg2 + t + 4];
            }
#pragma unroll
            for (int nf = 0; nf < 8; nf++) {
                int n = wn + nf * 8 + g;
                unsigned b0 = wb[n * WSB + kb2 + t];
                unsigned b1 = wb[n * WSB + kb2 + t + 4];
#pragma unroll
                for (int mf = 0; mf < 2; mf++)
                    mma16(acc[mf][nf], a_[mf], b0, b1);
            }
        }
        __syncthreads();
    }

    {   // prefetch W2 chunk 0
        int n = tid >> 2, j = tid & 3;
        cp16((char*)wsl + n * 80 + j * 16, (const char*)g_W2t + n * 512 + j * 16);
        CP_COMMIT();
    }

    // epilogue 1: + acc1 (has ugb), relu, fp16 -> hs
#pragma unroll
    for (int mf = 0; mf < 2; mf++) {
        int r0 = wm + mf * 16 + g;
        int r1 = r0 + 8;
        int node0 = base + r0;
        int node1 = base + r1;
#pragma unroll
        for (int nf = 0; nf < 8; nf++) {
            int n0 = wn + nf * 8 + 2 * t;
            float2 a0 = make_float2(0.f, 0.f), a1 = make_float2(0.f, 0.f);
            if (node0 < N_NODES) a0 = *(const float2*)(g_acc1 + (size_t)node0 * 256 + n0);
            if (node1 < N_NODES) a1 = *(const float2*)(g_acc1 + (size_t)node1 * 256 + n0);
            float f0 = fmaxf(acc[mf][nf][0] + a0.x, 0.f);
            float f1 = fmaxf(acc[mf][nf][1] + a0.y, 0.f);
            float f2 = fmaxf(acc[mf][nf][2] + a1.x, 0.f);
            float f3 = fmaxf(acc[mf][nf][3] + a1.y, 0.f);
            __half2 p0 = __floats2half2_rn(f0, f1);
            __half2 p1 = __floats2half2_rn(f2, f3);
            hs[r0 * HS2 + (n0 >> 1)] = *(unsigned*)&p0;
            hs[r1 * HS2 + (n0 >> 1)] = *(unsigned*)&p1;
        }
    }
    __syncthreads();

    // GEMM2: [128,256]@[256,128]
    const int wn2 = (wid & 3) * 32;
    float acc2[2][4][4];
#pragma unroll
    for (int a = 0; a < 2; a++)
#pragma unroll
        for (int b = 0; b < 4; b++)
#pragma unroll
            for (int q = 0; q < 4; q++) acc2[a][b][q] = 0.f;

#pragma unroll 1
    for (int c = 0; c < 8; c++) {
        if (c < 7) {
            unsigned* dst = wsl + ((c + 1) & 1) * B2BUF;
            const char* src = (const char*)g_W2t + (c + 1) * 64;
            {
                int q = tid;
                int n = q >> 2, j = q & 3;
                cp16((char*)dst + n * 80 + j * 16, src + n * 512 + j * 16);
            }
            CP_COMMIT(); CP_WAIT(1);
        } else {
            CP_WAIT(0);
        }
        __syncthreads();
        const unsigned* wb = wsl + (c & 1) * B2BUF;
#pragma unroll
        for (int ks = 0; ks < 2; ks++) {
            const int kg2 = c * 16 + ks * 8;
            const int kb2 = ks * 8;
            unsigned a_[2][4];
#pragma unroll
            for (int mf = 0; mf < 2; mf++) {
                int r0 = (wm + mf * 16 + g) * HS2;
                int r1 = r0 + 8 * HS2;
                a_[mf][0] = hs[r0 + kg2 + t];
                a_[mf][1] = hs[r1 + kg2 + t];
                a_[mf][2] = hs[r0 + kg2 + t + 4];
                a_[mf][3] = hs[r1 + kg2 + t + 4];
            }
#pragma unroll
            for (int nf = 0; nf < 4; nf++) {
                int n = wn2 + nf * 8 + g;
                unsigned b0 = wb[n * WSB + kb2 + t];
                unsigned b1 = wb[n * WSB + kb2 + t + 4];
#pragma unroll
                for (int mf = 0; mf < 2; mf++)
                    mma16(acc2[mf][nf], a_[mf], b0, b1);
            }
        }
        __syncthreads();
    }

    // epilogue 2: + b2 + x residual -> out
#pragma unroll
    for (int mf = 0; mf < 2; mf++) {
        int r0 = wm + mf * 16 + g;
        int r1 = r0 + 8;
        int node0 = base + r0;
        int node1 = base + r1;
#pragma unroll
        for (int nf = 0; nf < 4; nf++) {
            int col = wn2 + nf * 8 + 2 * t;
            if (node0 < N_NODES) {
                float2 xv = *(const float2*)(x + (size_t)node0 * 128 + col);
                float2 o;
                o.x = acc2[mf][nf][0] + b2s[col] + xv.x;
                o.y = acc2[mf][nf][1] + b2s[col + 1] + xv.y;
                *(float2*)(out + (size_t)node0 * 128 + col) = o;
            }
            if (node1 < N_NODES) {
                float2 xv = *(const float2*)(x + (size_t)node1 * 128 + col);
                float2 o;
                o.x = acc2[mf][nf][2] + b2s[col] + xv.x;
                o.y = acc2[mf][nf][3] + b2s[col + 1] + xv.y;
                *(float2*)(out + (size_t)node1 * 128 + col) = o;
            }
        }
    }
}

// ---------------- launch (fork-join: s2 runs prep+mlp_a under the scatter) ----------------
extern "C" void kernel_launch(void* const* d_in, const int* in_sizes, int n_in,
                              void* d_out, int out_size) {
    const float* x = nullptr; const int* edge_index = nullptr; const float* edge_attr = nullptr;
    const float* u = nullptr; const int* batch = nullptr;
    const float* W1 = nullptr; const float* b1 = nullptr;
    const float* W2 = nullptr; const float* b2 = nullptr;

    for (int i = 0; i < n_in; i++) {
        switch (in_sizes[i]) {
            case 12800000:  x          = (const float*)d_in[i]; break;
            case 3200000:   edge_index = (const int*)d_in[i];   break;
            case 204800000: edge_attr  = (const float*)d_in[i]; break;
            case 1024:      u          = (const float*)d_in[i]; break;
            case 100000:    batch      = (const int*)d_in[i];   break;
            case 69632:     W1         = (const float*)d_in[i]; break;
            case 256:       b1         = (const float*)d_in[i]; break;
            case 32768:     W2         = (const float*)d_in[i]; break;
            case 128:       b2         = (const float*)d_in[i]; break;
            default: break;
        }
    }
    float* out = (float*)d_out;
    const int* col = edge_index + N_EDGES;

    cudaFuncSetAttribute(mlp_a_kernel, cudaFuncAttributeMaxDynamicSharedMemorySize, SMA_TOTAL);
    cudaFuncSetAttribute(mlp_b_kernel, cudaFuncAttributeMaxDynamicSharedMemorySize, SMB_TOTAL);

    void* agg_ptr = nullptr;
    cudaGetSymbolAddress(&agg_ptr, g_agg);

    // kernel_launch is called only a handful of times (correctness + capture);
    // creating (and leaking) one stream + two events per call is bounded.
    cudaStream_t s2;
    cudaStreamCreateWithFlags(&s2, cudaStreamNonBlocking);
    cudaEvent_t e0, e2;
    cudaEventCreateWithFlags(&e0, cudaEventDisableTiming);
    cudaEventCreateWithFlags(&e2, cudaEventDisableTiming);

    // fork s2 off the main stream
    cudaEventRecord(e0, 0);
    cudaStreamWaitEvent(s2, e0, 0);

    // s2 branch: weights/ugb prep, then x-part GEMM1
    prep_kernel<<<448, 256, 0, s2>>>(W1, W2, u, b1);
    mlp_a_kernel<<<(N_NODES + 127) / 128, 512, SMA_TOTAL, s2>>>(x, batch);

    // main branch: zero agg, then edge scatter (RED-issue bound; tensor idle)
    cudaMemsetAsync(agg_ptr, 0, (size_t)N_NODES * 128 * sizeof(float));
    scatter_kernel<<<N_EDGES / 16, 256>>>(edge_attr, col);

    // join and finish
    cudaEventRecord(e2, s2);
    cudaStreamWaitEvent(0, e2, 0);
    mlp_b_kernel<<<(N_NODES + 127) / 128, 512, SMB_TOTAL>>>(x, b2, out);
}

// round 11
// speedup vs baseline: 1.4418x; 1.1524x over previous
#include <cuda_runtime.h>
#include <cuda_fp16.h>
#include <cstdint>

#define N_NODES 100000
#define N_EDGES 1600000
#define N_GRAPHS 64

// ---------------- device scratch (allocations forbidden) ----------------
__device__ __align__(16) __half g_aggh[(size_t)N_NODES * 128];  // 25.6 MB, fp16 accumulators
__device__ float g_ugb[N_GRAPHS * 256];                   // b1 + u@W1u per graph
__device__ __align__(16) __half g_W1t[256 * 256];         // W1[0:256]^T fp16, [n][k]
__device__ __align__(16) __half g_W2t[128 * 256];         // W2^T fp16, [n][k]

// ---------------- helpers ----------------
__device__ __forceinline__ void mma16(float* c, const unsigned* a, unsigned b0, unsigned b1) {
    asm volatile(
        "mma.sync.aligned.m16n8k16.row.col.f32.f16.f16.f32 "
        "{%0,%1,%2,%3}, {%4,%5,%6,%7}, {%8,%9}, {%0,%1,%2,%3};"
        : "+f"(c[0]), "+f"(c[1]), "+f"(c[2]), "+f"(c[3])
        : "r"(a[0]), "r"(a[1]), "r"(a[2]), "r"(a[3]), "r"(b0), "r"(b1));
}

__device__ __forceinline__ void cp16(void* dst_smem, const void* src) {
    unsigned d = (unsigned)__cvta_generic_to_shared(dst_smem);
    asm volatile("cp.async.ca.shared.global [%0], [%1], 16;" :: "r"(d), "l"(src) : "memory");
}
#define CP_COMMIT() asm volatile("cp.async.commit_group;" ::: "memory")
#define CP_WAIT(n)  asm volatile("cp.async.wait_group %0;" :: "n"(n) : "memory")

__device__ __forceinline__ unsigned pack2(float a, float b) {
    __half2 h = __floats2half2_rn(a, b);
    return *(unsigned*)&h;
}

__device__ __forceinline__ void red_v4_f16x2(__half* dst, unsigned r0, unsigned r1,
                                             unsigned r2, unsigned r3) {
    asm volatile("red.global.add.noftz.v4.f16x2 [%0], {%1, %2, %3, %4};"
                 :: "l"(dst), "r"(r0), "r"(r1), "r"(r2), "r"(r3) : "memory");
}

// ---------------- merged prep: W1^T fp16 | W2^T fp16 | ugb ----------------
__global__ void prep_kernel(const float* __restrict__ W1, const float* __restrict__ W2,
                            const float* __restrict__ u, const float* __restrict__ b1) {
    int bid = blockIdx.x;
    if (bid < 256) {
        int idx = bid * 256 + threadIdx.x;
        int n = idx >> 8, k = idx & 255;
        g_W1t[n * 256 + k] = __float2half_rn(W1[k * 256 + n]);
    } else if (bid < 384) {
        int idx = (bid - 256) * 256 + threadIdx.x;
        int n = idx >> 8, k = idx & 255;
        g_W2t[n * 256 + k] = __float2half_rn(W2[k * 128 + n]);
    } else {
        int g = bid - 384, n = threadIdx.x;
        float acc = b1[n];
#pragma unroll
        for (int j = 0; j < 16; j++) acc += u[g * 16 + j] * W1[(256 + j) * 256 + n];
        g_ugb[g * 256 + n] = acc;
    }
}

// ---------------- edge scatter: fp16 v4.f16x2 RED, 16 lanes/edge ----------------
// Each warp: 4 edges (2 per half-warp). Lane l of half-warp owns 8 floats -> 4 half2.
__global__ void scatter_kernel(const float* __restrict__ ea, const int* __restrict__ col) {
    int w  = blockIdx.x * 8 + (threadIdx.x >> 5);
    int hw = (threadIdx.x >> 4) & 1;
    int l  = threadIdx.x & 15;
    int e0 = w * 4 + hw;          // edges e0 and e0+2 for this half-warp
    int e1 = e0 + 2;
    int c0 = __ldg(col + e0);
    int c1 = __ldg(col + e1);
    const float4* p0 = (const float4*)(ea + (size_t)e0 * 128) + 2 * l;
    const float4* p1 = (const float4*)(ea + (size_t)e1 * 128) + 2 * l;
    float4 a0 = __ldcs(p0);
    float4 a1 = __ldcs(p0 + 1);
    float4 b0 = __ldcs(p1);
    float4 b1 = __ldcs(p1 + 1);
    unsigned r0 = pack2(a0.x, a0.y), r1 = pack2(a0.z, a0.w);
    unsigned r2 = pack2(a1.x, a1.y), r3 = pack2(a1.z, a1.w);
    unsigned s0 = pack2(b0.x, b0.y), s1 = pack2(b0.z, b0.w);
    unsigned s2 = pack2(b1.x, b1.y), s3 = pack2(b1.z, b1.w);
    if ((unsigned)c0 < N_NODES) red_v4_f16x2(g_aggh + (size_t)c0 * 128 + l * 8, r0, r1, r2, r3);
    if ((unsigned)c1 < N_NODES) red_v4_f16x2(g_aggh + (size_t)c1 * 128 + l * 8, s0, s1, s2, s3);
}

// ---------------- fused 2-layer MLP (fp16 mma, 512 threads/16 warps) ----------------
#define HS2 132
#define WSB 20
#define HS_BYTES (128 * HS2 * 4)
#define B1BUF (256 * WSB)
#define B2BUF (128 * WSB)
#define WSL_BYTES (2 * B1BUF * 4)
#define SMEM_TOTAL (HS_BYTES + WSL_BYTES + 1024)

__global__ void __launch_bounds__(512, 1) mlp_kernel(
    const float* __restrict__ x, const int* __restrict__ batch,
    const float* __restrict__ b2, float* __restrict__ out)
{
    extern __shared__ unsigned char sm[];
    unsigned* hs  = (unsigned*)sm;
    unsigned* wsl = (unsigned*)(sm + HS_BYTES);
    int*      gb  = (int*)(sm + HS_BYTES + WSL_BYTES);
    float*    b2s = (float*)(sm + HS_BYTES + WSL_BYTES + 512);

    const int tid  = threadIdx.x;
    const int wid  = tid >> 5;
    const int lane = tid & 31;
    const int g    = lane >> 2;
    const int t    = lane & 3;
    const int base = blockIdx.x * 128;
    const int wm   = (wid >> 2) * 32;
    const int wn   = (wid & 3) * 64;

    {
#pragma unroll
        for (int i = 0; i < 2; i++) {
            int q = tid + i * 512;
            int n = q >> 2, j = q & 3;
            cp16((char*)wsl + n * 80 + j * 16, (const char*)g_W1t + n * 512 + j * 16);
        }
        CP_COMMIT();
    }

    if (tid < 128) {
        int node = min(base + tid, N_NODES - 1);
        int gv = batch[node];
        gb[tid]  = min(max(gv, 0), N_GRAPHS - 1);
        b2s[tid] = b2[tid];
    }

    // fill hs: cols 0-127 = fp16(x), cols 128-255 = g_aggh (already fp16)
#pragma unroll
    for (int i = 0; i < 16; i++) {
        int uq = tid + i * 512;
        int r = uq >> 6, c4 = (uq & 63) << 2;
        int node = base + r;
        uint2 o = make_uint2(0u, 0u);
        if (node < N_NODES) {
            if (c4 < 128) {
                float4 v = __ldg((const float4*)(x + (size_t)node * 128 + c4));
                o.x = pack2(v.x, v.y);
                o.y = pack2(v.z, v.w);
            } else {
                o = __ldg((const uint2*)(g_aggh + (size_t)node * 128 + (c4 - 128)));
            }
        }
        *(uint2*)(hs + r * HS2 + (c4 >> 1)) = o;
    }

    float acc[2][8][4];
#pragma unroll
    for (int a = 0; a < 2; a++)
#pragma unroll
        for (int b = 0; b < 8; b++)
#pragma unroll
            for (int q = 0; q < 4; q++) acc[a][b][q] = 0.f;

#pragma unroll 1
    for (int c = 0; c < 8; c++) {
        if (c < 7) {
            unsigned* dst = wsl + ((c + 1) & 1) * B1BUF;
            const char* src = (const char*)g_W1t + (c + 1) * 64;
#pragma unroll
            for (int i = 0; i < 2; i++) {
                int q = tid + i * 512;
                int n = q >> 2, j = q & 3;
                cp16((char*)dst + n * 80 + j * 16, src + n * 512 + j * 16);
            }
            CP_COMMIT(); CP_WAIT(1);
        } else {
            CP_WAIT(0);
        }
        __syncthreads();
        const unsigned* wb = wsl + (c & 1) * B1BUF;
#pragma unroll
        for (int ks = 0; ks < 2; ks++) {
            const int kg2 = c * 16 + ks * 8;
            const int kb2 = ks * 8;
            unsigned a_[2][4];
#pragma unroll
            for (int mf = 0; mf < 2; mf++) {
                int r0 = (wm + mf * 16 + g) * HS2;
                int r1 = r0 + 8 * HS2;
                a_[mf][0] = hs[r0 + kg2 + t];
                a_[mf][1] = hs[r1 + kg2 + t];
                a_[mf][2] = hs[r0 + kg2 + t + 4];
                a_[mf][3] = hs[r1 + kg2 + t + 4];
            }
#pragma unroll
            for (int nf = 0; nf < 8; nf++) {
                int n = wn + nf * 8 + g;
                unsigned b0 = wb[n * WSB + kb2 + t];
                unsigned b1 = wb[n * WSB + kb2 + t + 4];
#pragma unroll
                for (int mf = 0; mf < 2; mf++)
                    mma16(acc[mf][nf], a_[mf], b0, b1);
            }
        }
        __syncthreads();
    }

    {
        int n = tid >> 2, j = tid & 3;
        cp16((char*)wsl + n * 80 + j * 16, (const char*)g_W2t + n * 512 + j * 16);
        CP_COMMIT();
    }

#pragma unroll
    for (int mf = 0; mf < 2; mf++) {
        int r0 = wm + mf * 16 + g;
        int r1 = r0 + 8;
        const float* u0 = g_ugb + gb[r0] * 256;
        const float* u1 = g_ugb + gb[r1] * 256;
#pragma unroll
        for (int nf = 0; nf < 8; nf++) {
            int n0 = wn + nf * 8 + 2 * t;
            float f0 = fmaxf(acc[mf][nf][0] + u0[n0], 0.f);
            float f1 = fmaxf(acc[mf][nf][1] + u0[n0 + 1], 0.f);
            float f2 = fmaxf(acc[mf][nf][2] + u1[n0], 0.f);
            float f3 = fmaxf(acc[mf][nf][3] + u1[n0 + 1], 0.f);
            hs[r0 * HS2 + (n0 >> 1)] = pack2(f0, f1);
            hs[r1 * HS2 + (n0 >> 1)] = pack2(f2, f3);
        }
    }
    __syncthreads();

    const int wn2 = (wid & 3) * 32;
    float acc2[2][4][4];
#pragma unroll
    for (int a = 0; a < 2; a++)
#pragma unroll
        for (int b = 0; b < 4; b++)
#pragma unroll
            for (int q = 0; q < 4; q++) acc2[a][b][q] = 0.f;

#pragma unroll 1
    for (int c = 0; c < 8; c++) {
        if (c < 7) {
            unsigned* dst = wsl + ((c + 1) & 1) * B2BUF;
            const char* src = (const char*)g_W2t + (c + 1) * 64;
            {
                int q = tid;
                int n = q >> 2, j = q & 3;
                cp16((char*)dst + n * 80 + j * 16, src + n * 512 + j * 16);
            }
            CP_COMMIT(); CP_WAIT(1);
        } else {
            CP_WAIT(0);
        }
        __syncthreads();
        const unsigned* wb = wsl + (c & 1) * B2BUF;
#pragma unroll
        for (int ks = 0; ks < 2; ks++) {
            const int kg2 = c * 16 + ks * 8;
            const int kb2 = ks * 8;
            unsigned a_[2][4];
#pragma unroll
            for (int mf = 0; mf < 2; mf++) {
                int r0 = (wm + mf * 16 + g) * HS2;
                int r1 = r0 + 8 * HS2;
                a_[mf][0] = hs[r0 + kg2 + t];
                a_[mf][1] = hs[r1 + kg2 + t];
                a_[mf][2] = hs[r0 + kg2 + t + 4];
                a_[mf][3] = hs[r1 + kg2 + t + 4];
            }
#pragma unroll
            for (int nf = 0; nf < 4; nf++) {
                int n = wn2 + nf * 8 + g;
                unsigned b0 = wb[n * WSB + kb2 + t];
                unsigned b1 = wb[n * WSB + kb2 + t + 4];
#pragma unroll
                for (int mf = 0; mf < 2; mf++)
                    mma16(acc2[mf][nf], a_[mf], b0, b1);
            }
        }
        __syncthreads();
    }

#pragma unroll
    for (int mf = 0; mf < 2; mf++) {
        int r0 = wm + mf * 16 + g;
        int r1 = r0 + 8;
        int node0 = base + r0;
        int node1 = base + r1;
#pragma unroll
        for (int nf = 0; nf < 4; nf++) {
            int col = wn2 + nf * 8 + 2 * t;
            if (node0 < N_NODES) {
                float2 xv = *(const float2*)(x + (size_t)node0 * 128 + col);
                float2 o;
                o.x = acc2[mf][nf][0] + b2s[col] + xv.x;
                o.y = acc2[mf][nf][1] + b2s[col + 1] + xv.y;
                *(float2*)(out + (size_t)node0 * 128 + col) = o;
            }
            if (node1 < N_NODES) {
                float2 xv = *(const float2*)(x + (size_t)node1 * 128 + col);
                float2 o;
                o.x = acc2[mf][nf][2] + b2s[col] + xv.x;
                o.y = acc2[mf][nf][3] + b2s[col + 1] + xv.y;
                *(float2*)(out + (size_t)node1 * 128 + col) = o;
            }
        }
    }
}

// ---------------- launch ----------------
extern "C" void kernel_launch(void* const* d_in, const int* in_sizes, int n_in,
                              void* d_out, int out_size) {
    const float* x = nullptr; const int* edge_index = nullptr; const float* edge_attr = nullptr;
    const float* u = nullptr; const int* batch = nullptr;
    const float* W1 = nullptr; const float* b1 = nullptr;
    const float* W2 = nullptr; const float* b2 = nullptr;

    for (int i = 0; i < n_in; i++) {
        switch (in_sizes[i]) {
            case 12800000:  x          = (const float*)d_in[i]; break;
            case 3200000:   edge_index = (const int*)d_in[i];   break;
            case 204800000: edge_attr  = (const float*)d_in[i]; break;
            case 1024:      u          = (const float*)d_in[i]; break;
            case 100000:    batch      = (const int*)d_in[i];   break;
            case 69632:     W1         = (const float*)d_in[i]; break;
            case 256:       b1         = (const float*)d_in[i]; break;
            case 32768:     W2         = (const float*)d_in[i]; break;
            case 128:       b2         = (const float*)d_in[i]; break;
            default: break;
        }
    }
    float* out = (float*)d_out;
    const int* col = edge_index + N_EDGES;

    cudaFuncSetAttribute(mlp_kernel, cudaFuncAttributeMaxDynamicSharedMemorySize, SMEM_TOTAL);

    void* agg_ptr = nullptr;
    cudaGetSymbolAddress(&agg_ptr, g_aggh);
    cudaMemsetAsync(agg_ptr, 0, (size_t)N_NODES * 128 * sizeof(__half));

    prep_kernel<<<448, 256>>>(W1, W2, u, b1);
    scatter_kernel<<<N_EDGES / 32, 256>>>(edge_attr, col);
    mlp_kernel<<<(N_NODES + 127) / 128, 512, SMEM_TOTAL>>>(x, batch, b2, out);
}